// round 9
// baseline (speedup 1.0000x reference)
#include <cuda_runtime.h>
#include <cuda_fp16.h>

// ---------------- problem constants ----------------
#define K_CODES 512
#define D_DIM   64
#define NPTS    65536          // 64*32*32
#define HW      1024           // 32*32
#define CHW     65536          // 64*1024
#define BETA_C  0.25f
#define DECAY_C 0.99f
#define OMD_C   0.01f
#define EPS_C   1e-5f
#define TAU     1e-4f          // rescue threshold (>3x worst-case fp16 3-term error)

// output layout (float32, tuple order)
#define OFF_Q    1
#define OFF_PERP 4194305
#define OFF_IDX  4194306
#define OFF_CS   4259842
#define OFF_W    4260354
#define OFF_E    4293122

// ---------------- scratch (zero-init at load; kernels restore zero) --------
__device__ float g_counts[K_CODES];
__device__ float g_dw[K_CODES * D_DIM];
__device__ float g_ncs[K_CODES];
__device__ float g_loss_acc;
__device__ float g_nrm[K_CODES];
__device__ int   g_rescue_pts[NPTS];
__device__ int   g_rescue_cnt;
__device__ __half g_Ah[NPTS * D_DIM];    // 8MB  x high fp16
__device__ __half g_Al[NPTS * D_DIM];    // 8MB  x residual fp16
__device__ __half g_Bh[K_CODES * D_DIM];
__device__ __half g_Bl[K_CODES * D_DIM];

// ---------------- helpers ----------------
__device__ __forceinline__ void red_add_v4(float* p, float a, float b, float c, float d) {
    asm volatile("red.global.add.v4.f32 [%0], {%1, %2, %3, %4};"
                 :: "l"(p), "f"(a), "f"(b), "f"(c), "f"(d) : "memory");
}
__device__ __forceinline__ unsigned smem_u32(const void* p) {
    unsigned a;
    asm("{ .reg .u64 t; cvta.to.shared.u64 t, %1; cvt.u32.u64 %0, t; }" : "=r"(a) : "l"(p));
    return a;
}
__device__ __forceinline__ unsigned pack_hf(__half a, __half b) {
    return (unsigned)__half_as_ushort(a) | ((unsigned)__half_as_ushort(b) << 16);
}
// monotonic float -> orderable uint mapping
__device__ __forceinline__ unsigned f2ord(float f) {
    unsigned u = __float_as_uint(f);
    return (u & 0x80000000u) ? ~u : (u | 0x80000000u);
}
#define SW128(o) ((o) ^ (((o) >> 3) & 0x70))

// warp-level fp16 MMA, fp32 accum (sm_80+ baseline PTX)
__device__ __forceinline__ void mma_f16(float* c, const unsigned* a,
                                        unsigned b0, unsigned b1) {
    asm volatile(
        "mma.sync.aligned.m16n8k16.row.col.f32.f16.f16.f32 "
        "{%0,%1,%2,%3}, {%4,%5,%6,%7}, {%8,%9}, {%0,%1,%2,%3};"
        : "+f"(c[0]), "+f"(c[1]), "+f"(c[2]), "+f"(c[3])
        : "r"(a[0]), "r"(a[1]), "r"(a[2]), "r"(a[3]), "r"(b0), "r"(b1));
}
__device__ __forceinline__ void ldmx2(unsigned& r0, unsigned& r1, unsigned saddr) {
    asm volatile("ldmatrix.sync.aligned.m8n8.x2.shared.b16 {%0,%1}, [%2];"
                 : "=r"(r0), "=r"(r1) : "r"(saddr));
}
__device__ __forceinline__ void upd(float& best, float& sec, int& idx, float d, int c) {
    if (d < best) { sec = best; best = d; idx = c; }
    else if (d < sec) { sec = d; }
}

// ---------------- K1a: convert x -> fp16 hi/lo, [point][dim] ----------------
__global__ __launch_bounds__(256)
void vq_conv_x(const float* __restrict__ in) {
    const int p  = blockIdx.x * 256 + threadIdx.x;
    const int b  = p >> 10, hw = p & 1023;
    const float* x = in + b * CHW + hw;
    uint4* Ah = (uint4*)g_Ah;
    uint4* Al = (uint4*)g_Al;
    #pragma unroll
    for (int j = 0; j < 8; ++j) {
        unsigned h[4], l[4];
        #pragma unroll
        for (int q = 0; q < 4; ++q) {
            float v0 = x[(8 * j + 2 * q) * HW];
            float v1 = x[(8 * j + 2 * q + 1) * HW];
            __half h0 = __float2half(v0), h1 = __float2half(v1);
            __half l0 = __float2half(v0 - __half2float(h0));
            __half l1 = __float2half(v1 - __half2float(h1));
            h[q] = pack_hf(h0, h1);
            l[q] = pack_hf(l0, l1);
        }
        Ah[p * 8 + j] = make_uint4(h[0], h[1], h[2], h[3]);
        Al[p * 8 + j] = make_uint4(l[0], l[1], l[2], l[3]);
    }
}

// ---------------- K1b: convert embedding -> fp16 hi/lo + fp32 norms --------
__global__ __launch_bounds__(128)
void vq_conv_e(const float* __restrict__ emb) {
    const int k = blockIdx.x * 128 + threadIdx.x;   // grid 4 -> 512
    const float* e = emb + k * D_DIM;
    uint4* Bh = (uint4*)g_Bh;
    uint4* Bl = (uint4*)g_Bl;
    float s = 0.0f;
    #pragma unroll
    for (int j = 0; j < 8; ++j) {
        unsigned h[4], l[4];
        #pragma unroll
        for (int q = 0; q < 4; ++q) {
            float v0 = e[8 * j + 2 * q];
            float v1 = e[8 * j + 2 * q + 1];
            s = fmaf(v0, v0, s);
            s = fmaf(v1, v1, s);
            __half h0 = __float2half(v0), h1 = __float2half(v1);
            __half l0 = __float2half(v0 - __half2float(h0));
            __half l1 = __float2half(v1 - __half2float(h1));
            h[q] = pack_hf(h0, h1);
            l[q] = pack_hf(l0, l1);
        }
        Bh[k * 8 + j] = make_uint4(h[0], h[1], h[2], h[3]);
        Bl[k * 8 + j] = make_uint4(l[0], l[1], l[2], l[3]);
    }
    g_nrm[k] = s;
}

// ---------------- K2: mma.sync GEMM + argmin -------------------------------
// 128 CTAs x 512 thr (16 warps). Each warp: 32 points (two m16 tiles), 512 codes.
// smem: nrm 2KB @0 | Bh 64KB @2048 | Bl 64KB @67584  -> 133120 B
#define SM_NRM 0
#define SM_BH  2048
#define SM_BL  67584
#define SMEM_SZ 133120

__global__ __launch_bounds__(512, 1)
void vq_gemm_argmin(float* __restrict__ out_idx) {
    extern __shared__ char smem[];
    const unsigned sb = smem_u32(smem);
    const int tid  = threadIdx.x;
    const int wid  = tid >> 5;
    const int lane = tid & 31;

    // stage codebook (swizzled) + norms once per CTA
    {
        const uint4* bh = (const uint4*)g_Bh;
        const uint4* bl = (const uint4*)g_Bl;
        #pragma unroll
        for (int i = tid; i < K_CODES * 8; i += 512) {
            unsigned off = SW128((unsigned)(i * 16));
            *(uint4*)(smem + SM_BH + off) = bh[i];
            *(uint4*)(smem + SM_BL + off) = bl[i];
        }
        float* nsh = (float*)(smem + SM_NRM);
        if (tid < K_CODES) nsh[tid] = g_nrm[tid];
    }
    __syncthreads();

    const float* nrm_sh = (const float*)(smem + SM_NRM);
    const int r    = lane & 7;
    const int half_ = (lane >> 3) & 1;
    const unsigned lane_rel = (unsigned)(r * 128);
    const unsigned qk = lane & 3;
    const unsigned qr = lane >> 2;

    const int p0 = blockIdx.x * 512 + wid * 32;   // 32 points per warp

    // A fragments for both 16-row tiles, 4 k-steps, hi+lo
    unsigned ah[2][16], al[2][16];
    #pragma unroll
    for (int t = 0; t < 2; ++t) {
        const __half* A0 = g_Ah + (size_t)(p0 + t * 16 + qr) * D_DIM;
        const __half* A1 = g_Al + (size_t)(p0 + t * 16 + qr) * D_DIM;
        #pragma unroll
        for (int kk = 0; kk < 4; ++kk) {
            const int e0 = kk * 16 + 2 * (int)qk;
            ah[t][kk*4+0] = *(const unsigned*)(A0 + e0);
            ah[t][kk*4+1] = *(const unsigned*)(A0 + 8 * D_DIM + e0);
            ah[t][kk*4+2] = *(const unsigned*)(A0 + e0 + 8);
            ah[t][kk*4+3] = *(const unsigned*)(A0 + 8 * D_DIM + e0 + 8);
            al[t][kk*4+0] = *(const unsigned*)(A1 + e0);
            al[t][kk*4+1] = *(const unsigned*)(A1 + 8 * D_DIM + e0);
            al[t][kk*4+2] = *(const unsigned*)(A1 + e0 + 8);
            al[t][kk*4+3] = *(const unsigned*)(A1 + 8 * D_DIM + e0 + 8);
        }
    }

    // slot s = t*2 + rowgroup (rowgroup 0: row qr, 1: row qr+8)
    float best[4] = {3.4e38f, 3.4e38f, 3.4e38f, 3.4e38f};
    float sec [4] = {3.4e38f, 3.4e38f, 3.4e38f, 3.4e38f};
    int   idx [4] = {0, 0, 0, 0};

    #pragma unroll 2
    for (int nt = 0; nt < 64; ++nt) {
        float c0[4] = {0.f, 0.f, 0.f, 0.f};
        float c1[4] = {0.f, 0.f, 0.f, 0.f};
        const unsigned ntoff = (unsigned)(nt * 1024) + lane_rel;
        #pragma unroll
        for (int kk = 0; kk < 4; ++kk) {
            const unsigned rel = ntoff + (((unsigned)(kk * 32 + half_ * 16)) ^ (unsigned)(r * 16));
            unsigned bh0, bh1, bl0, bl1;
            ldmx2(bh0, bh1, sb + SM_BH + rel);
            ldmx2(bl0, bl1, sb + SM_BL + rel);
            mma_f16(c0, &ah[0][kk*4], bh0, bh1);
            mma_f16(c0, &ah[0][kk*4], bl0, bl1);
            mma_f16(c0, &al[0][kk*4], bh0, bh1);
            mma_f16(c1, &ah[1][kk*4], bh0, bh1);
            mma_f16(c1, &ah[1][kk*4], bl0, bl1);
            mma_f16(c1, &al[1][kk*4], bh0, bh1);
        }
        const int colb = nt * 8 + 2 * (int)qk;
        const float n0 = nrm_sh[colb];
        const float n1 = nrm_sh[colb + 1];
        upd(best[0], sec[0], idx[0], fmaf(-2.f, c0[0], n0), colb);
        upd(best[0], sec[0], idx[0], fmaf(-2.f, c0[1], n1), colb + 1);
        upd(best[1], sec[1], idx[1], fmaf(-2.f, c0[2], n0), colb);
        upd(best[1], sec[1], idx[1], fmaf(-2.f, c0[3], n1), colb + 1);
        upd(best[2], sec[2], idx[2], fmaf(-2.f, c1[0], n0), colb);
        upd(best[2], sec[2], idx[2], fmaf(-2.f, c1[1], n1), colb + 1);
        upd(best[3], sec[3], idx[3], fmaf(-2.f, c1[2], n0), colb);
        upd(best[3], sec[3], idx[3], fmaf(-2.f, c1[3], n1), colb + 1);
    }

    // merge across the 4 lanes of each quad
    #pragma unroll
    for (int s = 0; s < 4; ++s) {
        #pragma unroll
        for (int o = 1; o <= 2; o <<= 1) {
            float ob = __shfl_xor_sync(0xFFFFFFFFu, best[s], o);
            float os = __shfl_xor_sync(0xFFFFFFFFu, sec[s],  o);
            int   oi = __shfl_xor_sync(0xFFFFFFFFu, idx[s],  o);
            if (ob < best[s] || (ob == best[s] && oi < idx[s])) {
                sec[s] = fminf(best[s], os); best[s] = ob; idx[s] = oi;
            } else sec[s] = fminf(sec[s], ob);
        }
    }

    if (qk == 0) {
        #pragma unroll
        for (int s = 0; s < 4; ++s) {
            const int p = p0 + (s >> 1) * 16 + (int)qr + (s & 1) * 8;
            out_idx[p] = (float)idx[s];
            if (sec[s] - best[s] < TAU) {
                int slot = atomicAdd(&g_rescue_cnt, 1);
                g_rescue_pts[slot] = p;
            }
        }
    }
}

// ---------------- K2b: exact fp32 rescue, one CTA per point ---------------
__global__ __launch_bounds__(256)
void vq_rescue(const float* __restrict__ in, const float* __restrict__ emb,
               float* __restrict__ out_idx) {
    __shared__ float xs[D_DIM];
    __shared__ unsigned long long red[256];
    const int tid = threadIdx.x;
    const int cnt = g_rescue_cnt;

    for (int itm = blockIdx.x; itm < cnt; itm += gridDim.x) {
        const int p  = g_rescue_pts[itm];
        const int b  = p >> 10, hw = p & 1023;
        if (tid < D_DIM) xs[tid] = __ldg(in + b * CHW + tid * HW + hw);
        __syncthreads();

        unsigned long long bestp = ~0ull;
        #pragma unroll
        for (int cc = 0; cc < 2; ++cc) {
            const int code = cc * 256 + tid;
            const float4* er = (const float4*)(emb + code * D_DIM);
            float s0 = 0.0f, s1 = 0.0f;
            #pragma unroll
            for (int j = 0; j < 16; ++j) {
                float4 e4 = __ldg(er + j);
                s0 = fmaf(xs[4 * j + 0], e4.x, s0);
                s1 = fmaf(xs[4 * j + 1], e4.y, s1);
                s0 = fmaf(xs[4 * j + 2], e4.z, s0);
                s1 = fmaf(xs[4 * j + 3], e4.w, s1);
            }
            const float d = fmaf(-2.0f, s0 + s1, __ldg(&g_nrm[code]));
            const unsigned long long pk =
                ((unsigned long long)f2ord(d) << 32) | (unsigned)code;
            bestp = (pk < bestp) ? pk : bestp;
        }
        red[tid] = bestp;
        __syncthreads();
        #pragma unroll
        for (int o = 128; o > 0; o >>= 1) {
            if (tid < o) {
                unsigned long long v = red[tid + o];
                if (v < red[tid]) red[tid] = v;
            }
            __syncthreads();
        }
        if (tid == 0) out_idx[p] = (float)(unsigned)(red[0] & 0xffffffffu);
        __syncthreads();
    }
}

// ---------------- K3: quantize + exact loss + segment sums ----------------
// 128 CTAs x 512 thr; fp32 codebook staged in smem with 4-float row rotation
__global__ __launch_bounds__(512, 1)
void vq_epilogue(const float* __restrict__ in, const float* __restrict__ emb,
                 const float* __restrict__ idxf, float* __restrict__ out_q) {
    extern __shared__ float es[];   // 32768 floats, rotated rows
    const int tid = threadIdx.x;

    for (int i = tid; i < K_CODES * D_DIM; i += 512) {
        const int k = i >> 6, c = i & 63;
        es[(k << 6) + ((c + 4 * k) & 63)] = emb[i];
    }
    __syncthreads();

    const int p  = blockIdx.x * 512 + tid;
    const int b  = p >> 10, hw = p & 1023;
    const float* xin = in + b * CHW + hw;
    const int best = (int)idxf[p];

    float*  qout  = out_q + b * CHW + hw;
    float*  dwrow = g_dw + best * D_DIM;
    const float* erow = es + (best << 6);
    const int rot = (4 * best) & 63;
    float lsum = 0.0f;
    #pragma unroll
    for (int j = 0; j < 16; ++j) {
        const int c = 4 * j;
        const float4 e4 = *(const float4*)(erow + ((c + rot) & 63));
        float x0 = xin[(c + 0) * HW];
        float x1 = xin[(c + 1) * HW];
        float x2 = xin[(c + 2) * HW];
        float x3 = xin[(c + 3) * HW];
        float d0 = e4.x - x0, d1 = e4.y - x1, d2 = e4.z - x2, d3 = e4.w - x3;
        qout[(c + 0) * HW] = x0 + d0;
        qout[(c + 1) * HW] = x1 + d1;
        qout[(c + 2) * HW] = x2 + d2;
        qout[(c + 3) * HW] = x3 + d3;
        lsum = fmaf(d0, d0, lsum); lsum = fmaf(d1, d1, lsum);
        lsum = fmaf(d2, d2, lsum); lsum = fmaf(d3, d3, lsum);
        red_add_v4(dwrow + c, x0, x1, x2, x3);
    }
    #pragma unroll
    for (int o = 16; o > 0; o >>= 1) lsum += __shfl_xor_sync(0xFFFFFFFFu, lsum, o);
    if ((tid & 31) == 0) atomicAdd(&g_loss_acc, lsum);
    atomicAdd(&g_counts[best], 1.0f);
}

// ---------------- K4a: single-CTA reductions + scalars --------------------
__global__ __launch_bounds__(512, 1)
void vq_finA_kernel(const float* __restrict__ ema_cs, float* __restrict__ out) {
    __shared__ float red[K_CODES];
    const int k = threadIdx.x;

    const float cnt = g_counts[k];
    const float raw = ema_cs[k] * DECAY_C + OMD_C * cnt;

    red[k] = raw;
    __syncthreads();
    #pragma unroll
    for (int o = 256; o > 0; o >>= 1) {
        if (k < o) red[k] += red[k + o];
        __syncthreads();
    }
    const float n = red[0];
    __syncthreads();

    const float ncs = (raw + EPS_C) / (n + (float)K_CODES * EPS_C) * n;
    g_ncs[k] = ncs;
    out[OFF_CS + k] = ncs;

    const float pprob = cnt * (1.0f / (float)NPTS);
    red[k] = pprob * logf(pprob + 1e-10f);
    __syncthreads();
    #pragma unroll
    for (int o = 256; o > 0; o >>= 1) {
        if (k < o) red[k] += red[k + o];
        __syncthreads();
    }
    if (k == 0) {
        out[OFF_PERP] = expf(-red[0]);
        out[0] = BETA_C * g_loss_acc / (float)(NPTS * D_DIM);
        g_loss_acc   = 0.0f;
        g_rescue_cnt = 0;
    }
    g_counts[k] = 0.0f;
}

// ---------------- K4b: parallel EMA-w / new-embedding ---------------------
__global__ __launch_bounds__(512)
void vq_finB_kernel(const float* __restrict__ ema_w, float* __restrict__ out) {
    const int i = blockIdx.x * 512 + threadIdx.x;   // < 32768
    const float w = ema_w[i] * DECAY_C + OMD_C * g_dw[i];
    g_dw[i] = 0.0f;
    out[OFF_W + i] = w;
    out[OFF_E + i] = w / g_ncs[i >> 6];
}

// ---------------- launch ----------------
extern "C" void kernel_launch(void* const* d_in, const int* in_sizes, int n_in,
                              void* d_out, int out_size) {
    const float* in     = (const float*)d_in[0];
    const float* emb    = (const float*)d_in[1];
    const float* ema_w  = (const float*)d_in[2];
    const float* ema_cs = (const float*)d_in[3];
    float* out = (float*)d_out;

    cudaFuncSetAttribute(vq_gemm_argmin,
                         cudaFuncAttributeMaxDynamicSharedMemorySize, SMEM_SZ);
    cudaFuncSetAttribute(vq_epilogue,
                         cudaFuncAttributeMaxDynamicSharedMemorySize,
                         K_CODES * D_DIM * (int)sizeof(float));

    vq_conv_x<<<256, 256>>>(in);
    vq_conv_e<<<4, 128>>>(emb);
    vq_gemm_argmin<<<128, 512, SMEM_SZ>>>(out + OFF_IDX);
    vq_rescue<<<256, 256>>>(in, emb, out + OFF_IDX);
    vq_epilogue<<<128, 512, K_CODES * D_DIM * sizeof(float)>>>(in, emb, out + OFF_IDX, out + OFF_Q);
    vq_finA_kernel<<<1, 512>>>(ema_cs, out);
    vq_finB_kernel<<<64, 512>>>(ema_w, out);
}

// round 10
// speedup vs baseline: 1.1628x; 1.1628x over previous
#include <cuda_runtime.h>
#include <cuda_fp16.h>

// ---------------- problem constants ----------------
#define K_CODES 512
#define D_DIM   64
#define NPTS    65536          // 64*32*32
#define HW      1024           // 32*32
#define CHW     65536          // 64*1024
#define BETA_C  0.25f
#define DECAY_C 0.99f
#define OMD_C   0.01f
#define EPS_C   1e-5f
#define TAU     1e-4f          // rescue threshold (>3x worst-case fp16 3-term error)

// output layout (float32, tuple order)
#define OFF_Q    1
#define OFF_PERP 4194305
#define OFF_IDX  4194306
#define OFF_CS   4259842
#define OFF_W    4260354
#define OFF_E    4293122

// ---------------- scratch (zero-init at load; kernels restore zero) --------
__device__ float g_counts[K_CODES];
__device__ float g_dw[K_CODES * D_DIM];
__device__ float g_ncs[K_CODES];
__device__ float g_loss_acc;
__device__ int   g_rescue_pts[NPTS];
__device__ int   g_rescue_cnt;

// ---------------- helpers ----------------
__device__ __forceinline__ void red_add_v4(float* p, float a, float b, float c, float d) {
    asm volatile("red.global.add.v4.f32 [%0], {%1, %2, %3, %4};"
                 :: "l"(p), "f"(a), "f"(b), "f"(c), "f"(d) : "memory");
}
__device__ __forceinline__ unsigned smem_u32(const void* p) {
    unsigned a;
    asm("{ .reg .u64 t; cvta.to.shared.u64 t, %1; cvt.u32.u64 %0, t; }" : "=r"(a) : "l"(p));
    return a;
}
__device__ __forceinline__ unsigned pack_hf(__half a, __half b) {
    return (unsigned)__half_as_ushort(a) | ((unsigned)__half_as_ushort(b) << 16);
}
// split fp32 -> (hi fp16, lo fp16) packed pair of two values
__device__ __forceinline__ void split2(float v0, float v1, unsigned& h, unsigned& l) {
    __half h0 = __float2half(v0), h1 = __float2half(v1);
    __half l0 = __float2half(v0 - __half2float(h0));
    __half l1 = __float2half(v1 - __half2float(h1));
    h = pack_hf(h0, h1);
    l = pack_hf(l0, l1);
}
// monotonic float -> orderable uint mapping
__device__ __forceinline__ unsigned f2ord(float f) {
    unsigned u = __float_as_uint(f);
    return (u & 0x80000000u) ? ~u : (u | 0x80000000u);
}
#define SW128(o) ((o) ^ (((o) >> 3) & 0x70))

// warp-level fp16 MMA, fp32 accum (sm_80+ baseline PTX)
__device__ __forceinline__ void mma_f16(float* c, const unsigned* a,
                                        unsigned b0, unsigned b1) {
    asm volatile(
        "mma.sync.aligned.m16n8k16.row.col.f32.f16.f16.f32 "
        "{%0,%1,%2,%3}, {%4,%5,%6,%7}, {%8,%9}, {%0,%1,%2,%3};"
        : "+f"(c[0]), "+f"(c[1]), "+f"(c[2]), "+f"(c[3])
        : "r"(a[0]), "r"(a[1]), "r"(a[2]), "r"(a[3]), "r"(b0), "r"(b1));
}
__device__ __forceinline__ void ldmx2(unsigned& r0, unsigned& r1, unsigned saddr) {
    asm volatile("ldmatrix.sync.aligned.m8n8.x2.shared.b16 {%0,%1}, [%2];"
                 : "=r"(r0), "=r"(r1) : "r"(saddr));
}
__device__ __forceinline__ void upd(float& best, float& sec, int& idx, float d, int c) {
    if (d < best) { sec = best; best = d; idx = c; }
    else if (d < sec) { sec = d; }
}

// ---------------- K1: fused convert + GEMM + argmin + epilogue -------------
// 128 CTAs x 512 thr (16 warps). Each warp: 32 points (two m16 tiles), 512 codes.
// smem: nrm 2KB @0 | idx 2KB @2048 | Bh 64KB @4096 | Bl 64KB @69632 -> 135168 B
#define SM_NRM 0
#define SM_IDX 2048
#define SM_BH  4096
#define SM_BL  69632
#define SMEM_SZ 135168

__global__ __launch_bounds__(512, 1)
void vq_fused(const float* __restrict__ in, const float* __restrict__ emb,
              float* __restrict__ out_q, float* __restrict__ out_idx) {
    extern __shared__ char smem[];
    const unsigned sb = smem_u32(smem);
    float* nrm_sh = (float*)(smem + SM_NRM);
    int*   sidx   = (int*)(smem + SM_IDX);
    const int tid  = threadIdx.x;
    const int wid  = tid >> 5;
    const int lane = tid & 31;

    // ---- stage B: convert fp32 codebook row 'tid' -> fp16 h/l swizzled smem
    {
        const float4* er = (const float4*)(emb + tid * D_DIM);
        float s = 0.0f;
        #pragma unroll
        for (int u = 0; u < 8; ++u) {
            float4 e0 = __ldg(er + 2 * u);
            float4 e1 = __ldg(er + 2 * u + 1);
            s = fmaf(e0.x, e0.x, s); s = fmaf(e0.y, e0.y, s);
            s = fmaf(e0.z, e0.z, s); s = fmaf(e0.w, e0.w, s);
            s = fmaf(e1.x, e1.x, s); s = fmaf(e1.y, e1.y, s);
            s = fmaf(e1.z, e1.z, s); s = fmaf(e1.w, e1.w, s);
            uint4 hq, lq;
            split2(e0.x, e0.y, hq.x, lq.x);
            split2(e0.z, e0.w, hq.y, lq.y);
            split2(e1.x, e1.y, hq.z, lq.z);
            split2(e1.z, e1.w, hq.w, lq.w);
            const unsigned off = SW128((unsigned)(tid * 128 + u * 16));
            *(uint4*)(smem + SM_BH + off) = hq;
            *(uint4*)(smem + SM_BL + off) = lq;
        }
        nrm_sh[tid] = s;
    }
    __syncthreads();

    const int r     = lane & 7;
    const int half_ = (lane >> 3) & 1;
    const unsigned lane_rel = (unsigned)(r * 128);
    const unsigned qk = lane & 3;
    const unsigned qr = lane >> 2;

    const int p0  = blockIdx.x * 512 + wid * 32;   // 32 points per warp
    const int b   = p0 >> 10;
    const int hw0 = p0 & 1023;

    // ---- A fragments straight from fp32 NCHW input, split h/l
    unsigned ah[2][16], al[2][16];
    #pragma unroll
    for (int t = 0; t < 2; ++t) {
        const int hwA = hw0 + t * 16 + (int)qr;     // row qr
        const int hwB = hwA + 8;                     // row qr+8
        const float* base = in + (size_t)b * CHW;
        #pragma unroll
        for (int kk = 0; kk < 4; ++kk) {
            const int c0 = kk * 16 + 2 * (int)qk;    // cols c0, c0+1
            const int c8 = c0 + 8;                   // cols c0+8, c0+9
            split2(base[(c0    ) * HW + hwA], base[(c0 + 1) * HW + hwA],
                   ah[t][kk*4+0], al[t][kk*4+0]);
            split2(base[(c0    ) * HW + hwB], base[(c0 + 1) * HW + hwB],
                   ah[t][kk*4+1], al[t][kk*4+1]);
            split2(base[(c8    ) * HW + hwA], base[(c8 + 1) * HW + hwA],
                   ah[t][kk*4+2], al[t][kk*4+2]);
            split2(base[(c8    ) * HW + hwB], base[(c8 + 1) * HW + hwB],
                   ah[t][kk*4+3], al[t][kk*4+3]);
        }
    }

    // slot s = t*2 + rowgroup (rowgroup 0: row qr, 1: row qr+8)
    float best[4] = {3.4e38f, 3.4e38f, 3.4e38f, 3.4e38f};
    float sec [4] = {3.4e38f, 3.4e38f, 3.4e38f, 3.4e38f};
    int   idx [4] = {0, 0, 0, 0};

    #pragma unroll 2
    for (int nt = 0; nt < 64; ++nt) {
        float c0[4] = {0.f, 0.f, 0.f, 0.f};
        float c1[4] = {0.f, 0.f, 0.f, 0.f};
        const unsigned ntoff = (unsigned)(nt * 1024) + lane_rel;
        #pragma unroll
        for (int kk = 0; kk < 4; ++kk) {
            const unsigned rel = ntoff + (((unsigned)(kk * 32 + half_ * 16)) ^ (unsigned)(r * 16));
            unsigned bh0, bh1, bl0, bl1;
            ldmx2(bh0, bh1, sb + SM_BH + rel);
            ldmx2(bl0, bl1, sb + SM_BL + rel);
            mma_f16(c0, &ah[0][kk*4], bh0, bh1);
            mma_f16(c0, &ah[0][kk*4], bl0, bl1);
            mma_f16(c0, &al[0][kk*4], bh0, bh1);
            mma_f16(c1, &ah[1][kk*4], bh0, bh1);
            mma_f16(c1, &ah[1][kk*4], bl0, bl1);
            mma_f16(c1, &al[1][kk*4], bh0, bh1);
        }
        const int colb = nt * 8 + 2 * (int)qk;
        const float n0 = nrm_sh[colb];
        const float n1 = nrm_sh[colb + 1];
        upd(best[0], sec[0], idx[0], fmaf(-2.f, c0[0], n0), colb);
        upd(best[0], sec[0], idx[0], fmaf(-2.f, c0[1], n1), colb + 1);
        upd(best[1], sec[1], idx[1], fmaf(-2.f, c0[2], n0), colb);
        upd(best[1], sec[1], idx[1], fmaf(-2.f, c0[3], n1), colb + 1);
        upd(best[2], sec[2], idx[2], fmaf(-2.f, c1[0], n0), colb);
        upd(best[2], sec[2], idx[2], fmaf(-2.f, c1[1], n1), colb + 1);
        upd(best[3], sec[3], idx[3], fmaf(-2.f, c1[2], n0), colb);
        upd(best[3], sec[3], idx[3], fmaf(-2.f, c1[3], n1), colb + 1);
    }

    // merge across the 4 lanes of each quad
    #pragma unroll
    for (int s = 0; s < 4; ++s) {
        #pragma unroll
        for (int o = 1; o <= 2; o <<= 1) {
            float ob = __shfl_xor_sync(0xFFFFFFFFu, best[s], o);
            float os = __shfl_xor_sync(0xFFFFFFFFu, sec[s],  o);
            int   oi = __shfl_xor_sync(0xFFFFFFFFu, idx[s],  o);
            if (ob < best[s] || (ob == best[s] && oi < idx[s])) {
                sec[s] = fminf(best[s], os); best[s] = ob; idx[s] = oi;
            } else sec[s] = fminf(sec[s], ob);
        }
    }

    if (qk == 0) {
        #pragma unroll
        for (int s = 0; s < 4; ++s) {
            const int lp = wid * 32 + (s >> 1) * 16 + (int)qr + (s & 1) * 8;
            const int p  = blockIdx.x * 512 + lp;
            out_idx[p] = (float)idx[s];
            const bool resc = (sec[s] - best[s] < TAU);
            sidx[lp] = idx[s] | (resc ? 0x80000000 : 0);
            if (resc) {
                int slot = atomicAdd(&g_rescue_cnt, 1);
                g_rescue_pts[slot] = p;
            }
        }
    }
    __syncthreads();

    // ---- fused epilogue: quantize + exact loss + segment sums (skip rescued)
    {
        const int p  = blockIdx.x * 512 + tid;
        const int bb = p >> 10, hw = p & 1023;
        const float* xin = in + (size_t)bb * CHW + hw;
        const int v = sidx[tid];
        float lsum = 0.0f;
        if (v >= 0) {
            const float4* erow  = (const float4*)(emb + (v << 6));
            float*        qout  = out_q + (size_t)bb * CHW + hw;
            float*        dwrow = g_dw + v * D_DIM;
            #pragma unroll
            for (int j = 0; j < 16; ++j) {
                float4 e4 = __ldg(erow + j);
                const int c = 4 * j;
                float x0 = xin[(c + 0) * HW];
                float x1 = xin[(c + 1) * HW];
                float x2 = xin[(c + 2) * HW];
                float x3 = xin[(c + 3) * HW];
                float d0 = e4.x - x0, d1 = e4.y - x1, d2 = e4.z - x2, d3 = e4.w - x3;
                qout[(c + 0) * HW] = x0 + d0;
                qout[(c + 1) * HW] = x1 + d1;
                qout[(c + 2) * HW] = x2 + d2;
                qout[(c + 3) * HW] = x3 + d3;
                lsum = fmaf(d0, d0, lsum); lsum = fmaf(d1, d1, lsum);
                lsum = fmaf(d2, d2, lsum); lsum = fmaf(d3, d3, lsum);
                red_add_v4(dwrow + c, x0, x1, x2, x3);
            }
            atomicAdd(&g_counts[v], 1.0f);
        }
        #pragma unroll
        for (int o = 16; o > 0; o >>= 1) lsum += __shfl_xor_sync(0xFFFFFFFFu, lsum, o);
        if (lane == 0) atomicAdd(&g_loss_acc, lsum);
    }
}

// ---------------- K2: exact fp32 rescue + full epilogue, one CTA per point -
__global__ __launch_bounds__(256)
void vq_rescue(const float* __restrict__ in, const float* __restrict__ emb,
               float* __restrict__ out_idx, float* __restrict__ out_q) {
    __shared__ float xs[D_DIM];
    __shared__ unsigned long long red[256];
    const int tid = threadIdx.x;
    const int cnt = g_rescue_cnt;

    for (int itm = blockIdx.x; itm < cnt; itm += gridDim.x) {
        const int p  = g_rescue_pts[itm];
        const int b  = p >> 10, hw = p & 1023;
        if (tid < D_DIM) xs[tid] = __ldg(in + (size_t)b * CHW + tid * HW + hw);
        __syncthreads();

        unsigned long long bestp = ~0ull;
        #pragma unroll
        for (int cc = 0; cc < 2; ++cc) {
            const int code = cc * 256 + tid;
            const float4* er = (const float4*)(emb + code * D_DIM);
            float s = 0.0f;
            #pragma unroll
            for (int j = 0; j < 16; ++j) {
                float4 e4 = __ldg(er + j);
                float d0 = xs[4 * j + 0] - e4.x;
                float d1 = xs[4 * j + 1] - e4.y;
                float d2 = xs[4 * j + 2] - e4.z;
                float d3 = xs[4 * j + 3] - e4.w;
                s = fmaf(d0, d0, s); s = fmaf(d1, d1, s);
                s = fmaf(d2, d2, s); s = fmaf(d3, d3, s);
            }
            const unsigned long long pk =
                ((unsigned long long)f2ord(s) << 32) | (unsigned)code;
            bestp = (pk < bestp) ? pk : bestp;
        }
        red[tid] = bestp;
        __syncthreads();
        #pragma unroll
        for (int o = 128; o > 0; o >>= 1) {
            if (tid < o) {
                unsigned long long v = red[tid + o];
                if (v < red[tid]) red[tid] = v;
            }
            __syncthreads();
        }
        const int bi = (int)(unsigned)(red[0] & 0xffffffffu);

        // full epilogue for this rescued point
        if (tid == 0) {
            out_idx[p] = (float)bi;
            atomicAdd(&g_counts[bi], 1.0f);
        }
        float lsum = 0.0f;
        if (tid < D_DIM) {
            const float e = __ldg(emb + bi * D_DIM + tid);
            const float x = xs[tid];
            const float d = e - x;
            out_q[(size_t)b * CHW + tid * HW + hw] = x + d;
            atomicAdd(&g_dw[bi * D_DIM + tid], x);
            lsum = d * d;
        }
        if (tid < D_DIM) {
            #pragma unroll
            for (int o = 16; o > 0; o >>= 1)
                lsum += __shfl_xor_sync(0xFFFFFFFFu, lsum, o);
            if ((tid & 31) == 0) atomicAdd(&g_loss_acc, lsum);
        }
        __syncthreads();
    }
}

// ---------------- K3a: single-CTA reductions + scalars --------------------
__global__ __launch_bounds__(512, 1)
void vq_finA_kernel(const float* __restrict__ ema_cs, float* __restrict__ out) {
    __shared__ float red[K_CODES];
    const int k = threadIdx.x;

    const float cnt = g_counts[k];
    const float raw = ema_cs[k] * DECAY_C + OMD_C * cnt;

    red[k] = raw;
    __syncthreads();
    #pragma unroll
    for (int o = 256; o > 0; o >>= 1) {
        if (k < o) red[k] += red[k + o];
        __syncthreads();
    }
    const float n = red[0];
    __syncthreads();

    const float ncs = (raw + EPS_C) / (n + (float)K_CODES * EPS_C) * n;
    g_ncs[k] = ncs;
    out[OFF_CS + k] = ncs;

    const float pprob = cnt * (1.0f / (float)NPTS);
    red[k] = pprob * logf(pprob + 1e-10f);
    __syncthreads();
    #pragma unroll
    for (int o = 256; o > 0; o >>= 1) {
        if (k < o) red[k] += red[k + o];
        __syncthreads();
    }
    if (k == 0) {
        out[OFF_PERP] = expf(-red[0]);
        out[0] = BETA_C * g_loss_acc / (float)(NPTS * D_DIM);
        g_loss_acc   = 0.0f;
        g_rescue_cnt = 0;
    }
    g_counts[k] = 0.0f;
}

// ---------------- K3b: parallel EMA-w / new-embedding ---------------------
__global__ __launch_bounds__(512)
void vq_finB_kernel(const float* __restrict__ ema_w, float* __restrict__ out) {
    const int i = blockIdx.x * 512 + threadIdx.x;   // < 32768
    const float w = ema_w[i] * DECAY_C + OMD_C * g_dw[i];
    g_dw[i] = 0.0f;
    out[OFF_W + i] = w;
    out[OFF_E + i] = w / g_ncs[i >> 6];
}

// ---------------- launch ----------------
extern "C" void kernel_launch(void* const* d_in, const int* in_sizes, int n_in,
                              void* d_out, int out_size) {
    const float* in     = (const float*)d_in[0];
    const float* emb    = (const float*)d_in[1];
    const float* ema_w  = (const float*)d_in[2];
    const float* ema_cs = (const float*)d_in[3];
    float* out = (float*)d_out;

    cudaFuncSetAttribute(vq_fused,
                         cudaFuncAttributeMaxDynamicSharedMemorySize, SMEM_SZ);

    vq_fused<<<128, 512, SMEM_SZ>>>(in, emb, out + OFF_Q, out + OFF_IDX);
    vq_rescue<<<128, 256>>>(in, emb, out + OFF_IDX, out + OFF_Q);
    vq_finA_kernel<<<1, 512>>>(ema_cs, out);
    vq_finB_kernel<<<64, 512>>>(ema_w, out);
}